// round 5
// baseline (speedup 1.0000x reference)
#include <cuda_runtime.h>
#include <cuda_fp16.h>
#include <cstdint>

#define BATCH 64
#define DIM   524288
#define PROJ  8192
#define CVAL  4
#define BCAP  512          // per-bucket capacity (mean 256, Poisson tail @512 ~ 1e-46)

#define NTRANS (DIM / 64)   // 8192 transpose CTAs
#define NPLACE (DIM / 256)  // 2048 place CTAs

// ----------------------------- device scratch ------------------------------
__device__ __align__(16) unsigned short g_xh[(size_t)DIM * BATCH]; // fp16 xT[d][b], 64 MB
__device__ unsigned g_entries[(size_t)PROJ * BCAP];                // 16 MB
__device__ int g_cursor[PROJ];   // static zero-init; reset by gather each run

// ---------------------------------------------------------------------------
// Kernel 1 (fused): CTAs [0, NTRANS) transpose x[64][DIM] fp32 -> xT fp16;
//                   CTAs [NTRANS, NTRANS+NPLACE) bucket-place instances.
// ---------------------------------------------------------------------------
__global__ void __launch_bounds__(256)
prep_kernel(const float* __restrict__ x,
            const int* __restrict__ idx, const int* __restrict__ sgn) {
    __shared__ float tile[64][65];

    if (blockIdx.x >= NTRANS) {
        // ---- place part: one thread per d, 4 instances -> buckets ----
        const int d = (blockIdx.x - NTRANS) * 256 + threadIdx.x;
        const int4 iv = reinterpret_cast<const int4*>(idx)[d];
        const int4 sv = reinterpret_cast<const int4*>(sgn)[d];
        const unsigned rec = (unsigned)d << 1;
        int p, pos;
        p = iv.x; pos = atomicAdd(&g_cursor[p], 1);
        if (pos < BCAP) g_entries[(size_t)p * BCAP + pos] = rec | sv.x;
        p = iv.y; pos = atomicAdd(&g_cursor[p], 1);
        if (pos < BCAP) g_entries[(size_t)p * BCAP + pos] = rec | sv.y;
        p = iv.z; pos = atomicAdd(&g_cursor[p], 1);
        if (pos < BCAP) g_entries[(size_t)p * BCAP + pos] = rec | sv.z;
        p = iv.w; pos = atomicAdd(&g_cursor[p], 1);
        if (pos < BCAP) g_entries[(size_t)p * BCAP + pos] = rec | sv.w;
        return;
    }

    // ---- transpose part: 64 d-columns x 64 batch rows per CTA ----
    const int d0 = blockIdx.x * 64;
    const int t  = threadIdx.x;

    // Phase 1: coalesced read (16 x float4 per row chunk), scalar smem store.
    {
        const int col = (t & 15) * 4;
        const int b0  = t >> 4;            // 0..15
        #pragma unroll
        for (int r = 0; r < 4; r++) {
            const int b = r * 16 + b0;
            float4 v = *reinterpret_cast<const float4*>(x + (size_t)b * DIM + d0 + col);
            tile[col + 0][b] = v.x;
            tile[col + 1][b] = v.y;
            tile[col + 2][b] = v.z;
            tile[col + 3][b] = v.w;
        }
    }
    __syncthreads();

    // Phase 2: convert + coalesced write (32B per thread, 8 full rows / warp).
    {
        const int dd   = t >> 2;
        const int part = t & 3;
        __half2 h[8];
        #pragma unroll
        for (int j = 0; j < 8; j++) {
            h[j] = __floats2half2_rn(tile[dd][part * 16 + 2 * j],
                                     tile[dd][part * 16 + 2 * j + 1]);
        }
        uint4* dst = reinterpret_cast<uint4*>(g_xh + (size_t)(d0 + dd) * 64 + part * 16);
        dst[0] = *reinterpret_cast<uint4*>(&h[0]);
        dst[1] = *reinterpret_cast<uint4*>(&h[4]);
    }
}

// ---------------------------------------------------------------------------
// Kernel 2: gather. One warp per bucket p; 4 entry-groups x 8 lanes per row.
// Unrolled x4 so 16 rows are in flight per warp (L2-latency hiding).
// ---------------------------------------------------------------------------
__device__ __forceinline__ void accum8(float (&acc)[8], uint4 raw, unsigned rec) {
    const float s = (rec & 1u) ? 1.0f : -1.0f;
    const float2 f0 = __half22float2(*reinterpret_cast<const __half2*>(&raw.x));
    const float2 f1 = __half22float2(*reinterpret_cast<const __half2*>(&raw.y));
    const float2 f2 = __half22float2(*reinterpret_cast<const __half2*>(&raw.z));
    const float2 f3 = __half22float2(*reinterpret_cast<const __half2*>(&raw.w));
    acc[0] = fmaf(s, f0.x, acc[0]);
    acc[1] = fmaf(s, f0.y, acc[1]);
    acc[2] = fmaf(s, f1.x, acc[2]);
    acc[3] = fmaf(s, f1.y, acc[3]);
    acc[4] = fmaf(s, f2.x, acc[4]);
    acc[5] = fmaf(s, f2.y, acc[5]);
    acc[6] = fmaf(s, f3.x, acc[6]);
    acc[7] = fmaf(s, f3.y, acc[7]);
}

__global__ void __launch_bounds__(256)
gather_kernel(float* __restrict__ out) {
    __shared__ float s_res[64][8];

    const int warp = threadIdx.x >> 5;
    const int lane = threadIdx.x & 31;
    const int p    = blockIdx.x * 8 + warp;
    const int g    = lane >> 3;      // entry group 0..3
    const int sub  = lane & 7;       // batch octet 0..7

    const int count = g_cursor[p];
    const unsigned* __restrict__ ent = g_entries + (size_t)p * BCAP;
    const unsigned short* __restrict__ xh = g_xh;

    float acc[8] = {0.f, 0.f, 0.f, 0.f, 0.f, 0.f, 0.f, 0.f};

    int i = g;
    // Main loop: 4 entries per group per iteration, all row loads issued first.
    for (; i + 12 < count; i += 16) {
        const unsigned r0 = ent[i];
        const unsigned r1 = ent[i + 4];
        const unsigned r2 = ent[i + 8];
        const unsigned r3 = ent[i + 12];
        const uint4 a0 = *reinterpret_cast<const uint4*>(xh + ((size_t)(r0 >> 1) << 6) + (sub << 3));
        const uint4 a1 = *reinterpret_cast<const uint4*>(xh + ((size_t)(r1 >> 1) << 6) + (sub << 3));
        const uint4 a2 = *reinterpret_cast<const uint4*>(xh + ((size_t)(r2 >> 1) << 6) + (sub << 3));
        const uint4 a3 = *reinterpret_cast<const uint4*>(xh + ((size_t)(r3 >> 1) << 6) + (sub << 3));
        accum8(acc, a0, r0);
        accum8(acc, a1, r1);
        accum8(acc, a2, r2);
        accum8(acc, a3, r3);
    }
    for (; i < count; i += 4) {
        const unsigned r = ent[i];
        const uint4 a = *reinterpret_cast<const uint4*>(xh + ((size_t)(r >> 1) << 6) + (sub << 3));
        accum8(acc, a, r);
    }

    // Reset this bucket's cursor for the next launch (static init covers run 0).
    if (lane == 0) g_cursor[p] = 0;

    // Reduce the 4 entry-groups (lanes l, l^8, l^16, l^24 share `sub`).
    #pragma unroll
    for (int k = 0; k < 8; k++) {
        acc[k] += __shfl_xor_sync(0xFFFFFFFFu, acc[k], 8);
        acc[k] += __shfl_xor_sync(0xFFFFFFFFu, acc[k], 16);
    }

    if (lane < 8) {
        #pragma unroll
        for (int k = 0; k < 8; k++)
            s_res[sub * 8 + k][warp] = 0.5f * acc[k];   // scale 1/sqrt(4)
    }
    __syncthreads();

    // Coalesced store: thread t writes float2 of out[b][p0 + part*2].
    {
        const int b    = threadIdx.x >> 2;
        const int part = threadIdx.x & 3;
        float2 v = make_float2(s_res[b][part * 2], s_res[b][part * 2 + 1]);
        *reinterpret_cast<float2*>(out + (size_t)b * PROJ + blockIdx.x * 8 + part * 2) = v;
    }
}

extern "C" void kernel_launch(void* const* d_in, const int* in_sizes, int n_in,
                              void* d_out, int out_size) {
    const float* x   = (const float*)d_in[0];
    const int*   idx = (const int*)d_in[1];
    const int*   sgn = (const int*)d_in[2];
    float*       out = (float*)d_out;

    prep_kernel<<<NTRANS + NPLACE, 256>>>(x, idx, sgn);
    gather_kernel<<<PROJ / 8, 256>>>(out);
}